// round 14
// baseline (speedup 1.0000x reference)
#include <cuda_runtime.h>
#include <cuda_fp16.h>
#include <cuda_bf16.h>
#include <math.h>
#include <stdint.h>

// Problem constants
#define N_TOK 2048
#define D_MOD 2048
#define NHEAD 16
#define DHEAD 128
#define NQ    256
#define EPS   1e-5f

// ---------------- device scratch ----------------
__device__ __half         g_xnh [N_TOK * D_MOD];
__device__ __half         g_wqT [D_MOD * D_MOD];
__device__ __half         g_wkT [D_MOD * D_MOD];
__device__ __half         g_wvT [D_MOD * D_MOD];
__device__ __half         g_woT [D_MOD * D_MOD];
__device__ __half         g_vh  [N_TOK * D_MOD];
__device__ __nv_bfloat16  g_kbf [N_TOK * D_MOD];
__device__ __nv_bfloat16  g_qbf [NQ * D_MOD];
__device__ __half         g_oh  [NQ * D_MOD];

// ---------------- helpers ----------------
__device__ __forceinline__ uint32_t smem_u32(const void* p) {
    uint32_t a;
    asm("{ .reg .u64 t; cvta.to.shared.u64 t, %1; cvt.u32.u64 %0, t; }" : "=r"(a) : "l"(p));
    return a;
}
__device__ __forceinline__ void cpa16(uint32_t saddr, const void* gaddr) {
    asm volatile("cp.async.cg.shared.global [%0], [%1], 16;" :: "r"(saddr), "l"(gaddr));
}
__device__ __forceinline__ void ldsm4(uint32_t addr, uint32_t* r) {
    asm volatile("ldmatrix.sync.aligned.m8n8.x4.shared.b16 {%0,%1,%2,%3}, [%4];"
                 : "=r"(r[0]), "=r"(r[1]), "=r"(r[2]), "=r"(r[3]) : "r"(addr));
}
__device__ __forceinline__ void mma16816(float* c, const uint32_t* a, const uint32_t* b) {
    asm volatile("mma.sync.aligned.m16n8k16.row.col.f32.f16.f16.f32 "
        "{%0,%1,%2,%3}, {%4,%5,%6,%7}, {%8,%9}, {%0,%1,%2,%3};"
        : "+f"(c[0]), "+f"(c[1]), "+f"(c[2]), "+f"(c[3])
        : "r"(a[0]), "r"(a[1]), "r"(a[2]), "r"(a[3]), "r"(b[0]), "r"(b[1]));
}
__device__ __forceinline__ uint32_t swz(uint32_t off) {
    return off ^ ((off >> 3) & 0x70);
}

// ================ prep: LN(x)->fp16  +  4 weight transposes (64x64 tiles) =========
__global__ __launch_bounds__(256)
void prep(const float* __restrict__ x, __half* __restrict__ xh,
          const float* __restrict__ W0, const float* __restrict__ W1,
          const float* __restrict__ W2, const float* __restrict__ W3,
          __half* __restrict__ T0, __half* __restrict__ T1,
          __half* __restrict__ T2, __half* __restrict__ T3) {
    __shared__ float tile[64][65];
    __shared__ float bs[8], bss[8];
    int bid = blockIdx.x;
    int tid = threadIdx.x;

    if (bid < 2048) {
        int row = bid;
        const float4* xr = (const float4*)(x + (size_t)row * D_MOD);
        float4 a = xr[tid];
        float4 b = xr[tid + 256];
        float s  = a.x + a.y + a.z + a.w + b.x + b.y + b.z + b.w;
        float ss = a.x*a.x + a.y*a.y + a.z*a.z + a.w*a.w
                 + b.x*b.x + b.y*b.y + b.z*b.z + b.w*b.w;
        #pragma unroll
        for (int o = 16; o > 0; o >>= 1) {
            s  += __shfl_xor_sync(0xffffffffu, s,  o);
            ss += __shfl_xor_sync(0xffffffffu, ss, o);
        }
        int w = tid >> 5, l = tid & 31;
        if (l == 0) { bs[w] = s; bss[w] = ss; }
        __syncthreads();
        float ts = 0.f, tss = 0.f;
        #pragma unroll
        for (int i = 0; i < 8; i++) { ts += bs[i]; tss += bss[i]; }
        float mean = ts * (1.0f / D_MOD);
        float var  = tss * (1.0f / D_MOD) - mean * mean;
        float inv  = rsqrtf(var + EPS);
        __half2* hp = (__half2*)(xh + (size_t)row * D_MOD);
        hp[tid*2 + 0]   = __floats2half2_rn((a.x - mean) * inv, (a.y - mean) * inv);
        hp[tid*2 + 1]   = __floats2half2_rn((a.z - mean) * inv, (a.w - mean) * inv);
        hp[512 + tid*2] = __floats2half2_rn((b.x - mean) * inv, (b.y - mean) * inv);
        hp[513 + tid*2] = __floats2half2_rn((b.z - mean) * inv, (b.w - mean) * inv);
    } else {
        int t = bid - 2048;
        int which = t >> 10;
        int rem = t & 1023;
        int bx = rem & 31, by = rem >> 5;
        const float* W = (which == 0) ? W0 : (which == 1) ? W1 : (which == 2) ? W2 : W3;
        __half* T = (which == 0) ? T0 : (which == 1) ? T1 : (which == 2) ? T2 : T3;
        int rr = tid >> 4, c4 = tid & 15;
        #pragma unroll
        for (int p = 0; p < 4; p++) {
            int r = rr + p * 16;
            float4 v = *(const float4*)(W + (size_t)(by*64 + r) * D_MOD + bx*64 + c4*4);
            tile[r][c4*4 + 0] = v.x;
            tile[r][c4*4 + 1] = v.y;
            tile[r][c4*4 + 2] = v.z;
            tile[r][c4*4 + 3] = v.w;
        }
        __syncthreads();
        #pragma unroll
        for (int p = 0; p < 2; p++) {
            int idx = tid + p * 256;
            int nl = idx >> 3, c8 = idx & 7;
            __half2 h0 = __floats2half2_rn(tile[c8*8 + 0][nl], tile[c8*8 + 1][nl]);
            __half2 h1 = __floats2half2_rn(tile[c8*8 + 2][nl], tile[c8*8 + 3][nl]);
            __half2 h2 = __floats2half2_rn(tile[c8*8 + 4][nl], tile[c8*8 + 5][nl]);
            __half2 h3 = __floats2half2_rn(tile[c8*8 + 6][nl], tile[c8*8 + 7][nl]);
            uint4 pk;
            pk.x = *(uint32_t*)&h0; pk.y = *(uint32_t*)&h1;
            pk.z = *(uint32_t*)&h2; pk.w = *(uint32_t*)&h3;
            *(uint4*)(T + (size_t)(bx*64 + nl) * D_MOD + by*64 + c8*8) = pk;
        }
    }
}

// ================ fused projections: K+V per CTA (shared A), Q, hidden copies ====
// bid < 256 : K+V fused 128x128 tile (A loaded once for both weights)
// bid < 288 : Q (head-LN -> bf16, M=256, 2x16 tiles)
// bid < 304 : init out[0:256] = x[0:256]     (16 blocks x 8 iters x 1024 float4)
// bid < 336 : tail copy out[256:] = x[256:]  (32 blocks x 28 iters x 1024 float4)
#define NSTAGE 32
#define STG_KV 49152          // A 16KB | Bk 16KB | Bv 16KB
#define PROJ_SMEM (2 * STG_KV)

__global__ __launch_bounds__(256)
void proj_gemm(const __half* __restrict__ A,
               const __half* __restrict__ WK, const __half* __restrict__ WV,
               const __half* __restrict__ WQ,
               __nv_bfloat16* __restrict__ Kout, __half* __restrict__ Vout,
               __nv_bfloat16* __restrict__ Qout,
               const float* __restrict__ x, float* __restrict__ out) {
    int bid = blockIdx.x;
    int tid = threadIdx.x;

    if (bid >= 288) {
        if (bid < 304) {
            const float4* xs = (const float4*)x;
            float4* od = (float4*)out;
            size_t base = (size_t)(bid - 288) * 8192;
            #pragma unroll 1
            for (int it = 0; it < 8; it++) {
                size_t i = base + (size_t)it * 1024 + tid;
                float4 a0 = xs[i], a1 = xs[i + 256], a2 = xs[i + 512], a3 = xs[i + 768];
                od[i] = a0; od[i + 256] = a1; od[i + 512] = a2; od[i + 768] = a3;
            }
        } else {
            // 32 blocks x 28 iters x 1024 = 917504 float4 = rows [256,2048)
            const float4* xs = (const float4*)(x + (size_t)NQ * D_MOD);
            float4* od = (float4*)(out + (size_t)NQ * D_MOD);
            size_t base = (size_t)(bid - 304) * 28672;
            #pragma unroll 1
            for (int it = 0; it < 28; it++) {
                size_t i = base + (size_t)it * 1024 + tid;
                float4 a0 = xs[i], a1 = xs[i + 256], a2 = xs[i + 512], a3 = xs[i + 768];
                od[i] = a0; od[i + 256] = a1; od[i + 512] = a2; od[i + 768] = a3;
            }
        }
        return;
    }

    extern __shared__ __align__(1024) char smem[];
    uint32_t sb = smem_u32(smem);
    int wid = tid >> 5, lane = tid & 31;
    int wr = wid >> 2, wc = wid & 3;

    if (bid < 256) {
        // ======== K+V fused: 128x128 tile, shared A ========
        int tx = bid & 15, ty = bid >> 4;
        int rowBase = ty * 128, colBase = tx * 128;

        float accK[4][4][4], accV[4][4][4];
        #pragma unroll
        for (int mi = 0; mi < 4; mi++)
            #pragma unroll
            for (int ni = 0; ni < 4; ni++)
                #pragma unroll
                for (int r = 0; r < 4; r++) { accK[mi][ni][r] = 0.f; accV[mi][ni][r] = 0.f; }

        auto load_stage = [&](int s, int buf) {
            uint32_t so = sb + (uint32_t)buf * STG_KV;
            size_t kof = (size_t)s * 64;
            #pragma unroll
            for (int p = 0; p < 4; p++) {
                int chunk = tid + p * 256;
                int row = chunk >> 3, c = chunk & 7;
                uint32_t sw = swz((uint32_t)(row * 128 + c * 16));
                size_t gb = (size_t)(colBase + row) * 2048 + kof + c * 8;
                cpa16(so + sw,         A  + (size_t)(rowBase + row) * 2048 + kof + c * 8);
                cpa16(so + 16384 + sw, WK + gb);
                cpa16(so + 32768 + sw, WV + gb);
            }
            asm volatile("cp.async.commit_group;" ::: "memory");
        };

        load_stage(0, 0);
        load_stage(1, 1);

        for (int s = 0; s < NSTAGE; s++) {
            if (s + 2 < NSTAGE) asm volatile("cp.async.wait_group 1;" ::: "memory");
            else                asm volatile("cp.async.wait_group 0;" ::: "memory");
            __syncthreads();
            uint32_t so = sb + (uint32_t)(s & 1) * STG_KV;
            #pragma unroll
            for (int ks = 0; ks < 4; ks++) {
                uint32_t ah[4][4], bk[2][4], bv[2][4];
                #pragma unroll
                for (int mi = 0; mi < 4; mi++) {
                    int row = wr * 64 + mi * 16 + (lane & 15);
                    int ch  = ks * 2 + (lane >> 4);
                    ldsm4(so + swz((uint32_t)(row * 128 + ch * 16)), ah[mi]);
                }
                #pragma unroll
                for (int p = 0; p < 2; p++) {
                    int row = wc * 32 + p * 16 + ((lane >> 4) << 3) + (lane & 7);
                    int ch  = ks * 2 + ((lane >> 3) & 1);
                    uint32_t sw = swz((uint32_t)(row * 128 + ch * 16));
                    ldsm4(so + 16384 + sw, bk[p]);
                    ldsm4(so + 32768 + sw, bv[p]);
                }
                #pragma unroll
                for (int mi = 0; mi < 4; mi++)
                    #pragma unroll
                    for (int ni = 0; ni < 4; ni++) {
                        mma16816(accK[mi][ni], ah[mi], &bk[ni >> 1][(ni & 1) * 2]);
                        mma16816(accV[mi][ni], ah[mi], &bv[ni >> 1][(ni & 1) * 2]);
                    }
            }
            __syncthreads();
            if (s + 2 < NSTAGE) load_stage(s + 2, s & 1);
        }

        // ---- V epilogue: fp16 store ----
        #pragma unroll
        for (int mi = 0; mi < 4; mi++)
            #pragma unroll
            for (int ni = 0; ni < 4; ni++) {
                int m0  = rowBase + wr * 64 + mi * 16 + (lane >> 2);
                int col = colBase + wc * 32 + ni * 8 + (lane & 3) * 2;
                size_t i0 = (size_t)m0 * 2048 + col;
                size_t i1 = i0 + (size_t)8 * 2048;
                *(__half2*)(Vout + i0) = __floats2half2_rn(accK ? accV[mi][ni][0] : 0.f, accV[mi][ni][1]);
                *(__half2*)(Vout + i1) = __floats2half2_rn(accV[mi][ni][2], accV[mi][ni][3]);
            }

        // ---- K epilogue: per-head LN -> bf16 ----
        float sv[4][2], qv[4][2];
        #pragma unroll
        for (int mi = 0; mi < 4; mi++)
            #pragma unroll
            for (int h = 0; h < 2; h++) {
                float s = 0.f, q = 0.f;
                #pragma unroll
                for (int ni = 0; ni < 4; ni++) {
                    float a0 = accK[mi][ni][h*2 + 0], a1 = accK[mi][ni][h*2 + 1];
                    s += a0 + a1;
                    q += a0*a0 + a1*a1;
                }
                s += __shfl_xor_sync(0xffffffffu, s, 1);
                s += __shfl_xor_sync(0xffffffffu, s, 2);
                q += __shfl_xor_sync(0xffffffffu, q, 1);
                q += __shfl_xor_sync(0xffffffffu, q, 2);
                sv[mi][h] = s;
                qv[mi][h] = q;
            }
        __syncthreads();
        float* sArr = (float*)smem;
        float* qArr = ((float*)smem) + 512;
        if ((lane & 3) == 0) {
            #pragma unroll
            for (int mi = 0; mi < 4; mi++)
                #pragma unroll
                for (int h = 0; h < 2; h++) {
                    int row = wr * 64 + mi * 16 + (lane >> 2) + h * 8;
                    sArr[wc * 128 + row] = sv[mi][h];
                    qArr[wc * 128 + row] = qv[mi][h];
                }
        }
        __syncthreads();
        #pragma unroll
        for (int mi = 0; mi < 4; mi++)
            #pragma unroll
            for (int h = 0; h < 2; h++) {
                int row = wr * 64 + mi * 16 + (lane >> 2) + h * 8;
                float S = sArr[row] + sArr[128 + row] + sArr[256 + row] + sArr[384 + row];
                float Q = qArr[row] + qArr[128 + row] + qArr[256 + row] + qArr[384 + row];
                float mean = S * (1.0f / 128.0f);
                float var  = Q * (1.0f / 128.0f) - mean * mean;
                float inv  = rsqrtf(var + EPS);
                int m = rowBase + row;
                #pragma unroll
                for (int ni = 0; ni < 4; ni++) {
                    int col = colBase + wc * 32 + ni * 8 + (lane & 3) * 2;
                    float a0 = (accK[mi][ni][h*2 + 0] - mean) * inv;
                    float a1 = (accK[mi][ni][h*2 + 1] - mean) * inv;
                    *(__nv_bfloat162*)(Kout + (size_t)m * 2048 + col) = __floats2bfloat162_rn(a0, a1);
                }
            }
        return;
    }

    // ======== Q: single-B 128x128 tile (2x16) ========
    {
        int qb = bid - 256;
        int tx = qb & 15, ty = qb >> 4;
        int rowBase = ty * 128, colBase = tx * 128;

        float acc[4][4][4];
        #pragma unroll
        for (int mi = 0; mi < 4; mi++)
            #pragma unroll
            for (int ni = 0; ni < 4; ni++)
                #pragma unroll
                for (int r = 0; r < 4; r++) acc[mi][ni][r] = 0.f;

        auto load_stage = [&](int s, int buf) {
            uint32_t so = sb + (uint32_t)buf * STG_KV;   // reuse stride; only 32KB used
            size_t kof = (size_t)s * 64;
            #pragma unroll
            for (int p = 0; p < 4; p++) {
                int chunk = tid + p * 256;
                int row = chunk >> 3, c = chunk & 7;
                uint32_t sw = swz((uint32_t)(row * 128 + c * 16));
                cpa16(so + sw,         A  + (size_t)(rowBase + row) * 2048 + kof + c * 8);
                cpa16(so + 16384 + sw, WQ + (size_t)(colBase + row) * 2048 + kof + c * 8);
            }
            asm volatile("cp.async.commit_group;" ::: "memory");
        };

        load_stage(0, 0);
        load_stage(1, 1);

        for (int s = 0; s < NSTAGE; s++) {
            if (s + 2 < NSTAGE) asm volatile("cp.async.wait_group 1;" ::: "memory");
            else                asm volatile("cp.async.wait_group 0;" ::: "memory");
            __syncthreads();
            uint32_t so = sb + (uint32_t)(s & 1) * STG_KV;
            #pragma unroll
            for (int ks = 0; ks < 4; ks++) {
                uint32_t ah[4][4], bh[2][4];
                #pragma unroll
                for (int mi = 0; mi < 4; mi++) {
                    int row = wr * 64 + mi * 16 + (lane & 15);
                    int ch  = ks * 2 + (lane >> 4);
                    ldsm4(so + swz((uint32_t)(row * 128 + ch * 16)), ah[mi]);
                }
                #pragma unroll
                for (int p = 0; p < 2; p++) {
                    int row = wc * 32 + p * 16 + ((lane >> 4) << 3) + (lane & 7);
                    int ch  = ks * 2 + ((lane >> 3) & 1);
                    ldsm4(so + 16384 + swz((uint32_t)(row * 128 + ch * 16)), bh[p]);
                }
                #pragma unroll
                for (int mi = 0; mi < 4; mi++)
                    #pragma unroll
                    for (int ni = 0; ni < 4; ni++)
                        mma16816(acc[mi][ni], ah[mi], &bh[ni >> 1][(ni & 1) * 2]);
            }
            __syncthreads();
            if (s + 2 < NSTAGE) load_stage(s + 2, s & 1);
        }

        float sv[4][2], qv[4][2];
        #pragma unroll
        for (int mi = 0; mi < 4; mi++)
            #pragma unroll
            for (int h = 0; h < 2; h++) {
                float s = 0.f, q = 0.f;
                #pragma unroll
                for (int ni = 0; ni < 4; ni++) {
                    float a0 = acc[mi][ni][h*2 + 0], a1 = acc[mi][ni][h*2 + 1];
                    s += a0 + a1;
                    q += a0*a0 + a1*a1;
                }
                s += __shfl_xor_sync(0xffffffffu, s, 1);
                s += __shfl_xor_sync(0xffffffffu, s, 2);
                q += __shfl_xor_sync(0xffffffffu, q, 1);
                q += __shfl_xor_sync(0xffffffffu, q, 2);
                sv[mi][h] = s;
                qv[mi][h] = q;
            }
        __syncthreads();
        float* sArr = (float*)smem;
        float* qArr = ((float*)smem) + 512;
        if ((lane & 3) == 0) {
            #pragma unroll
            for (int mi = 0; mi < 4; mi++)
                #pragma unroll
                for (int h = 0; h < 2; h++) {
                    int row = wr * 64 + mi * 16 + (lane >> 2) + h * 8;
                    sArr[wc * 128 + row] = sv[mi][h];
                    qArr[wc * 128 + row] = qv[mi][h];
                }
        }
        __syncthreads();
        #pragma unroll
        for (int mi = 0; mi < 4; mi++)
            #pragma unroll
            for (int h = 0; h < 2; h++) {
                int row = wr * 64 + mi * 16 + (lane >> 2) + h * 8;
                float S = sArr[row] + sArr[128 + row] + sArr[256 + row] + sArr[384 + row];
                float Q = qArr[row] + qArr[128 + row] + qArr[256 + row] + qArr[384 + row];
                float mean = S * (1.0f / 128.0f);
                float var  = Q * (1.0f / 128.0f) - mean * mean;
                float inv  = rsqrtf(var + EPS);
                int m = rowBase + row;
                #pragma unroll
                for (int ni = 0; ni < 4; ni++) {
                    int col = colBase + wc * 32 + ni * 8 + (lane & 3) * 2;
                    float a0 = (acc[mi][ni][h*2 + 0] - mean) * inv;
                    float a1 = (acc[mi][ni][h*2 + 1] - mean) * inv;
                    *(__nv_bfloat162*)(Qout + (size_t)m * 2048 + col) = __floats2bfloat162_rn(a0, a1);
                }
            }
    }
}

// ================ sparse attention v4: block=(b,h), V in smem fp16 =============
#define KROWB 264
#define ATT4_SMEM (8192 + 8192 + 32768 + 128 * KROWB)

__global__ __launch_bounds__(256)
void attn4(const __nv_bfloat16* __restrict__ qbf, const __nv_bfloat16* __restrict__ kbf,
           const __half* __restrict__ v, __half* __restrict__ o) {
    extern __shared__ __align__(16) char asmem[];
    float* qs = (float*)asmem;
    float* ps = qs + 2048;
    __half* vsh = (__half*)(asmem + 16384);
    char*  ks = asmem + 16384 + 32768;
    __shared__ float redm[16][4], reds[16][4];
    int b = blockIdx.x, h = blockIdx.y;
    int tid = threadIdx.x, lane = tid & 31;
    int w4 = (tid >> 5) & 3;

    {
        int r = tid >> 4, c = tid & 15;
        uint4 qv = *(const uint4*)(qbf + (size_t)(16*b + r) * D_MOD + h * DHEAD + c * 8);
        const __nv_bfloat162* qb = (const __nv_bfloat162*)&qv;
        float2 f0 = __bfloat1622float2(qb[0]);
        float2 f1 = __bfloat1622float2(qb[1]);
        float2 f2 = __bfloat1622float2(qb[2]);
        float2 f3 = __bfloat1622float2(qb[3]);
        *(float4*)(qs + r * 128 + c * 8)     = make_float4(f0.x, f0.y, f1.x, f1.y);
        *(float4*)(qs + r * 128 + c * 8 + 4) = make_float4(f2.x, f2.y, f3.x, f3.y);
    }
    #pragma unroll
    for (int p = 0; p < 16; p++) {
        int idx = tid + p * 256;
        int j = idx >> 5, c = idx & 31;
        uint2 kk = *(const uint2*)(kbf + (size_t)(b + 16*j) * D_MOD + h * DHEAD + c * 4);
        *(uint2*)(ks + j * KROWB + c * 8) = kk;
    }
    #pragma unroll
    for (int p = 0; p < 16; p++) {
        int idx = tid + p * 256;
        int j = idx >> 5, c = idx & 31;
        uint2 vv = *(const uint2*)(v + (size_t)(b + 16*j) * D_MOD + h * DHEAD + c * 4);
        *(uint2*)(vsh + j * 128 + c * 4) = vv;
    }
    __syncthreads();

    int j = tid & 127, rh = tid >> 7;
    float s[8];
    #pragma unroll
    for (int r8 = 0; r8 < 8; r8++) s[r8] = 0.f;
    #pragma unroll 4
    for (int d4 = 0; d4 < 32; d4++) {
        uint2 kk = *(const uint2*)(ks + j * KROWB + d4 * 8);
        float2 k01 = __bfloat1622float2(*(const __nv_bfloat162*)&kk.x);
        float2 k23 = __bfloat1622float2(*(const __nv_bfloat162*)&kk.y);
        #pragma unroll
        for (int r8 = 0; r8 < 8; r8++) {
            float4 qv = *(const float4*)(qs + (rh * 8 + r8) * 128 + d4 * 4);
            s[r8] += qv.x * k01.x + qv.y * k01.y + qv.z * k23.x + qv.w * k23.y;
        }
    }
    const float SC = 0.08838834764831845f;
    #pragma unroll
    for (int r8 = 0; r8 < 8; r8++) s[r8] *= SC;

    #pragma unroll
    for (int r8 = 0; r8 < 8; r8++) {
        float m = s[r8];
        #pragma unroll
        for (int off = 16; off > 0; off >>= 1) m = fmaxf(m, __shfl_xor_sync(0xffffffffu, m, off));
        if (lane == 0) redm[rh * 8 + r8][w4] = m;
    }
    __syncthreads();
    #pragma unroll
    for (int r8 = 0; r8 < 8; r8++) {
        int r = rh * 8 + r8;
        float mx = fmaxf(fmaxf(redm[r][0], redm[r][1]), fmaxf(redm[r][2], redm[r][3]));
        float p = __expf(s[r8] - mx);
        ps[r * 128 + j] = p;
        float t = p;
        #pragma unroll
        for (int off = 16; off > 0; off >>= 1) t += __shfl_xor_sync(0xffffffffu, t, off);
        if (lane == 0) reds[r][w4] = t;
    }
    __syncthreads();
    float invr[8];
    #pragma unroll
    for (int r8 = 0; r8 < 8; r8++) {
        int r = rh * 8 + r8;
        invr[r8] = 1.0f / fmaxf(reds[r][0] + reds[r][1] + reds[r][2] + reds[r][3], 1e-30f);
    }

    int d = tid & 127;
    float acc[8];
    #pragma unroll
    for (int r8 = 0; r8 < 8; r8++) acc[r8] = 0.f;
    #pragma unroll 4
    for (int jj = 0; jj < 128; jj++) {
        float vv = __half2float(vsh[jj * 128 + d]);
        #pragma unroll
        for (int r8 = 0; r8 < 8; r8++)
            acc[r8] += ps[(rh * 8 + r8) * 128 + jj] * vv;
    }
    #pragma unroll
    for (int r8 = 0; r8 < 8; r8++) {
        int r = rh * 8 + r8;
        o[(size_t)(16*b + r) * D_MOD + h * DHEAD + d] = __float2half_rn(acc[r8] * invr[r8]);
    }
}

// ================ Wo GEMM: 128x128 tiles, split-K=4, atomic epilogue ============
// grid 128: kslice = bid>>5 covers k in [kslice*512, +512) = 8 stages of BK=64.
// rem = bid&31: rowtile = rem>>4 (2 of 128 rows), coltile = rem&15.
#define STG_WO 32768
#define WO_SMEM (2 * STG_WO)

__global__ __launch_bounds__(256)
void gemm_wo(const __half* __restrict__ A, const __half* __restrict__ B,
             float* __restrict__ C) {
    extern __shared__ __align__(1024) char smem[];
    uint32_t sb = smem_u32(smem);
    int bid = blockIdx.x;
    int tid = threadIdx.x;
    int wid = tid >> 5, lane = tid & 31;
    int wr = wid >> 2, wc = wid & 3;
    int kslice = bid >> 5;
    int rem = bid & 31;
    int rowBase = (rem >> 4) * 128, colBase = (rem & 15) * 128;
    size_t kBase = (size_t)kslice * 512;

    float acc[4][4][4];
    #pragma unroll
    for (int mi = 0; mi < 4; mi++)
        #pragma unroll
        for (int ni = 0; ni < 4; ni++)
            #pragma unroll
            for (int r = 0; r < 4; r++) acc[mi][ni][r] = 0.f;

    auto load_stage = [&](int s) {
        uint32_t so = sb + (uint32_t)(s & 1) * STG_WO;
        size_t kof = kBase + (size_t)s * 64;
        #pragma unroll
        for (int p = 0; p < 4; p++) {
            int chunk = tid + p * 256;
            int row = chunk >> 3, c = chunk & 7;
            uint32_t sw = swz((uint32_t)(row * 128 + c * 16));
            cpa16(so + sw,         A + (size_t)(rowBase + row) * 2048 + kof + c * 8);
            cpa16(so + 16384 + sw, B + (size_t)(colBase + row) * 2048 + kof + c * 8);
        }
        asm volatile("cp.async.commit_group;" ::: "memory");
    };

    load_stage(0);
    load_stage(1);

    #pragma unroll 1
    for (int s = 0; s < 8; s++) {
        if (s + 2 < 8) asm volatile("cp.async.wait_group 1;" ::: "memory");
        else           asm volatile("cp.async.wait_group 0;" ::: "memory");
        __syncthreads();
        uint32_t so = sb + (uint32_t)(s & 1) * STG_WO;
        #pragma unroll
        for (int ks = 0; ks < 4; ks++) {
            uint32_t ah[4][4], bh[2][4];
            #pragma unroll
            for (int mi = 0; mi < 4; mi++) {
                int row = wr * 64 + mi * 16 + (lane & 15);
                int ch  = ks * 2 + (lane >> 4);
                ldsm4(so + swz((uint32_t)(row * 128 + ch * 16)), ah[mi]);
            }
            #pragma unroll
            for (int p = 0; p < 2; p++) {
                int row = wc * 32 + p * 16 + ((lane >> 4) << 3) + (lane & 7);
                int ch  = ks * 2 + ((lane >> 3) & 1);
                ldsm4(so + 16384 + swz((uint32_t)(row * 128 + ch * 16)), bh[p]);
            }
            #pragma unroll
            for (int mi = 0; mi < 4; mi++)
                #pragma unroll
                for (int ni = 0; ni < 4; ni++)
                    mma16816(acc[mi][ni], ah[mi], &bh[ni >> 1][(ni & 1) * 2]);
        }
        __syncthreads();
        if (s + 2 < 8) load_stage(s + 2);
    }

    #pragma unroll
    for (int mi = 0; mi < 4; mi++)
        #pragma unroll
        for (int ni = 0; ni < 4; ni++) {
            int m0  = rowBase + wr * 64 + mi * 16 + (lane >> 2);
            int col = colBase + wc * 32 + ni * 8 + (lane & 3) * 2;
            size_t i0 = (size_t)m0 * 2048 + col;
            size_t i1 = i0 + (size_t)8 * 2048;
            atomicAdd(C + i0,     acc[mi][ni][0]);
            atomicAdd(C + i0 + 1, acc[mi][ni][1]);
            atomicAdd(C + i1,     acc[mi][ni][2]);
            atomicAdd(C + i1 + 1, acc[mi][ni][3]);
        }
}

extern "C" void kernel_launch(void* const* d_in, const int* in_sizes, int n_in,
                              void* d_out, int out_size) {
    const float* x  = (const float*)d_in[0];
    const float* Wq = (const float*)d_in[1];
    const float* Wk = (const float*)d_in[2];
    const float* Wv = (const float*)d_in[3];
    const float* Wo = (const float*)d_in[4];
    float* out = (float*)d_out;

    __half *xnh, *wqT, *wkT, *wvT, *woT, *oh, *vh;
    __nv_bfloat16 *kbf, *qbf;
    cudaGetSymbolAddress((void**)&xnh,  g_xnh);
    cudaGetSymbolAddress((void**)&wqT,  g_wqT);
    cudaGetSymbolAddress((void**)&wkT,  g_wkT);
    cudaGetSymbolAddress((void**)&wvT,  g_wvT);
    cudaGetSymbolAddress((void**)&woT,  g_woT);
    cudaGetSymbolAddress((void**)&vh,   g_vh);
    cudaGetSymbolAddress((void**)&kbf,  g_kbf);
    cudaGetSymbolAddress((void**)&qbf,  g_qbf);
    cudaGetSymbolAddress((void**)&oh,   g_oh);

    cudaFuncSetAttribute(proj_gemm, cudaFuncAttributeMaxDynamicSharedMemorySize, PROJ_SMEM);
    cudaFuncSetAttribute(gemm_wo,   cudaFuncAttributeMaxDynamicSharedMemorySize, WO_SMEM);
    cudaFuncSetAttribute(attn4,     cudaFuncAttributeMaxDynamicSharedMemorySize, ATT4_SMEM);

    // 1) LN -> fp16  +  all weight transposes
    prep<<<2048 + 4 * 1024, 256>>>(x, xnh, Wq, Wk, Wv, Wo, wqT, wkT, wvT, woT);
    // 2) K+V fused (shared A) + Q projections; residual copies hidden
    proj_gemm<<<336, 256, PROJ_SMEM>>>(xnh, wkT, wvT, wqT, kbf, vh, qbf, x, out);
    // 3) sparse attention -> fp16
    attn4<<<dim3(16, 16), 256, ATT4_SMEM>>>(qbf, kbf, vh, oh);
    // 4) out[0:256] += o @ Wo (128x128 tiles, split-K=4, atomic)
    gemm_wo<<<128, 256, WO_SMEM>>>(oh, woT, out);
}

// round 15
// speedup vs baseline: 1.0694x; 1.0694x over previous
#include <cuda_runtime.h>
#include <cuda_fp16.h>
#include <cuda_bf16.h>
#include <math.h>
#include <stdint.h>

// Problem constants
#define N_TOK 2048
#define D_MOD 2048
#define NHEAD 16
#define DHEAD 128
#define NQ    256
#define EPS   1e-5f

// ---------------- device scratch ----------------
__device__ __half         g_xnh [N_TOK * D_MOD];
__device__ __half         g_wqT [D_MOD * D_MOD];
__device__ __half         g_wkT [D_MOD * D_MOD];
__device__ __half         g_wvT [D_MOD * D_MOD];
__device__ __half         g_woT [D_MOD * D_MOD];
__device__ __half         g_vh  [N_TOK * D_MOD];
__device__ __nv_bfloat16  g_kbf [N_TOK * D_MOD];
__device__ __nv_bfloat16  g_qbf [NQ * D_MOD];
__device__ __half         g_oh  [NQ * D_MOD];

// ---------------- helpers ----------------
__device__ __forceinline__ uint32_t smem_u32(const void* p) {
    uint32_t a;
    asm("{ .reg .u64 t; cvta.to.shared.u64 t, %1; cvt.u32.u64 %0, t; }" : "=r"(a) : "l"(p));
    return a;
}
__device__ __forceinline__ void cpa16(uint32_t saddr, const void* gaddr) {
    asm volatile("cp.async.cg.shared.global [%0], [%1], 16;" :: "r"(saddr), "l"(gaddr));
}
__device__ __forceinline__ void ldsm4(uint32_t addr, uint32_t* r) {
    asm volatile("ldmatrix.sync.aligned.m8n8.x4.shared.b16 {%0,%1,%2,%3}, [%4];"
                 : "=r"(r[0]), "=r"(r[1]), "=r"(r[2]), "=r"(r[3]) : "r"(addr));
}
__device__ __forceinline__ void mma16816(float* c, const uint32_t* a, const uint32_t* b) {
    asm volatile("mma.sync.aligned.m16n8k16.row.col.f32.f16.f16.f32 "
        "{%0,%1,%2,%3}, {%4,%5,%6,%7}, {%8,%9}, {%0,%1,%2,%3};"
        : "+f"(c[0]), "+f"(c[1]), "+f"(c[2]), "+f"(c[3])
        : "r"(a[0]), "r"(a[1]), "r"(a[2]), "r"(a[3]), "r"(b[0]), "r"(b[1]));
}
__device__ __forceinline__ uint32_t swz(uint32_t off) {
    return off ^ ((off >> 3) & 0x70);
}

// ================ prep: LN(x)->fp16  +  4 weight transposes (64x64 tiles) =========
__global__ __launch_bounds__(256)
void prep(const float* __restrict__ x, __half* __restrict__ xh,
          const float* __restrict__ W0, const float* __restrict__ W1,
          const float* __restrict__ W2, const float* __restrict__ W3,
          __half* __restrict__ T0, __half* __restrict__ T1,
          __half* __restrict__ T2, __half* __restrict__ T3) {
    __shared__ float tile[64][65];
    __shared__ float bs[8], bss[8];
    int bid = blockIdx.x;
    int tid = threadIdx.x;

    if (bid < 2048) {
        int row = bid;
        const float4* xr = (const float4*)(x + (size_t)row * D_MOD);
        float4 a = xr[tid];
        float4 b = xr[tid + 256];
        float s  = a.x + a.y + a.z + a.w + b.x + b.y + b.z + b.w;
        float ss = a.x*a.x + a.y*a.y + a.z*a.z + a.w*a.w
                 + b.x*b.x + b.y*b.y + b.z*b.z + b.w*b.w;
        #pragma unroll
        for (int o = 16; o > 0; o >>= 1) {
            s  += __shfl_xor_sync(0xffffffffu, s,  o);
            ss += __shfl_xor_sync(0xffffffffu, ss, o);
        }
        int w = tid >> 5, l = tid & 31;
        if (l == 0) { bs[w] = s; bss[w] = ss; }
        __syncthreads();
        float ts = 0.f, tss = 0.f;
        #pragma unroll
        for (int i = 0; i < 8; i++) { ts += bs[i]; tss += bss[i]; }
        float mean = ts * (1.0f / D_MOD);
        float var  = tss * (1.0f / D_MOD) - mean * mean;
        float inv  = rsqrtf(var + EPS);
        __half2* hp = (__half2*)(xh + (size_t)row * D_MOD);
        hp[tid*2 + 0]   = __floats2half2_rn((a.x - mean) * inv, (a.y - mean) * inv);
        hp[tid*2 + 1]   = __floats2half2_rn((a.z - mean) * inv, (a.w - mean) * inv);
        hp[512 + tid*2] = __floats2half2_rn((b.x - mean) * inv, (b.y - mean) * inv);
        hp[513 + tid*2] = __floats2half2_rn((b.z - mean) * inv, (b.w - mean) * inv);
    } else {
        int t = bid - 2048;
        int which = t >> 10;
        int rem = t & 1023;
        int bx = rem & 31, by = rem >> 5;
        const float* W = (which == 0) ? W0 : (which == 1) ? W1 : (which == 2) ? W2 : W3;
        __half* T = (which == 0) ? T0 : (which == 1) ? T1 : (which == 2) ? T2 : T3;
        int rr = tid >> 4, c4 = tid & 15;
        #pragma unroll
        for (int p = 0; p < 4; p++) {
            int r = rr + p * 16;
            float4 v = *(const float4*)(W + (size_t)(by*64 + r) * D_MOD + bx*64 + c4*4);
            tile[r][c4*4 + 0] = v.x;
            tile[r][c4*4 + 1] = v.y;
            tile[r][c4*4 + 2] = v.z;
            tile[r][c4*4 + 3] = v.w;
        }
        __syncthreads();
        #pragma unroll
        for (int p = 0; p < 2; p++) {
            int idx = tid + p * 256;
            int nl = idx >> 3, c8 = idx & 7;
            __half2 h0 = __floats2half2_rn(tile[c8*8 + 0][nl], tile[c8*8 + 1][nl]);
            __half2 h1 = __floats2half2_rn(tile[c8*8 + 2][nl], tile[c8*8 + 3][nl]);
            __half2 h2 = __floats2half2_rn(tile[c8*8 + 4][nl], tile[c8*8 + 5][nl]);
            __half2 h3 = __floats2half2_rn(tile[c8*8 + 6][nl], tile[c8*8 + 7][nl]);
            uint4 pk;
            pk.x = *(uint32_t*)&h0; pk.y = *(uint32_t*)&h1;
            pk.z = *(uint32_t*)&h2; pk.w = *(uint32_t*)&h3;
            *(uint4*)(T + (size_t)(bx*64 + nl) * D_MOD + by*64 + c8*8) = pk;
        }
    }
}

// ================ fused projections Q/K/V + hidden residual copies ===============
// bid <  32 : Q (head-LN -> bf16, M=256)
// bid < 288 : K (head-LN -> bf16)
// bid < 544 : V (fp16)
// bid < 560 : init out[0:256] = x[0:256]       (16 blocks x 8 iters x 1024 float4)
// bid < 592 : tail copy out[256:] = x[256:]    (32 blocks x 28 iters x 1024 float4)
#define NSTAGE 32
#define STG128 32768
#define G128_SMEM (2 * STG128)

__global__ __launch_bounds__(256)
void proj_gemm(const __half* __restrict__ A,
               const __half* __restrict__ WK, const __half* __restrict__ WV,
               const __half* __restrict__ WQ,
               __nv_bfloat16* __restrict__ Kout, __half* __restrict__ Vout,
               __nv_bfloat16* __restrict__ Qout,
               const float* __restrict__ x, float* __restrict__ out) {
    int bid = blockIdx.x;
    int tid = threadIdx.x;

    if (bid >= 544) {
        if (bid < 560) {
            const float4* xs = (const float4*)x;
            float4* od = (float4*)out;
            size_t base = (size_t)(bid - 544) * 8192;
            #pragma unroll 1
            for (int it = 0; it < 8; it++) {
                size_t i = base + (size_t)it * 1024 + tid;
                float4 a0 = xs[i], a1 = xs[i + 256], a2 = xs[i + 512], a3 = xs[i + 768];
                od[i] = a0; od[i + 256] = a1; od[i + 512] = a2; od[i + 768] = a3;
            }
        } else {
            // 32 blocks x 28 iters x 1024 = 917504 float4 = rows [256,2048)
            const float4* xs = (const float4*)(x + (size_t)NQ * D_MOD);
            float4* od = (float4*)(out + (size_t)NQ * D_MOD);
            size_t base = (size_t)(bid - 560) * 28672;
            #pragma unroll 1
            for (int it = 0; it < 28; it++) {
                size_t i = base + (size_t)it * 1024 + tid;
                float4 a0 = xs[i], a1 = xs[i + 256], a2 = xs[i + 512], a3 = xs[i + 768];
                od[i] = a0; od[i + 256] = a1; od[i + 512] = a2; od[i + 768] = a3;
            }
        }
        return;
    }

    extern __shared__ __align__(1024) char smem[];
    uint32_t sb = smem_u32(smem);
    int wid = tid >> 5, lane = tid & 31;
    int wr = wid >> 2, wc = wid & 3;

    int mode, tx, ty;
    const __half* B;
    if (bid < 32)       { mode = 2; tx = bid & 15; ty = bid >> 4; B = WQ; }
    else if (bid < 288) { mode = 0; tx = (bid - 32) & 15; ty = (bid - 32) >> 4; B = WK; }
    else                { mode = 1; tx = (bid - 288) & 15; ty = (bid - 288) >> 4; B = WV; }
    int rowBase = ty * 128, colBase = tx * 128;

    float acc[4][4][4];
    #pragma unroll
    for (int mi = 0; mi < 4; mi++)
        #pragma unroll
        for (int ni = 0; ni < 4; ni++)
            #pragma unroll
            for (int r = 0; r < 4; r++) acc[mi][ni][r] = 0.f;

    auto load_stage = [&](int s, int buf) {
        uint32_t so = sb + (uint32_t)buf * STG128;
        size_t kof = (size_t)s * 64;
        #pragma unroll
        for (int p = 0; p < 4; p++) {
            int chunk = tid + p * 256;
            int row = chunk >> 3, c = chunk & 7;
            uint32_t sw = swz((uint32_t)(row * 128 + c * 16));
            cpa16(so + sw,         A + (size_t)(rowBase + row) * 2048 + kof + c * 8);
            cpa16(so + 16384 + sw, B + (size_t)(colBase + row) * 2048 + kof + c * 8);
        }
        asm volatile("cp.async.commit_group;" ::: "memory");
    };

    load_stage(0, 0);
    load_stage(1, 1);

    for (int s = 0; s < NSTAGE; s++) {
        if (s + 2 < NSTAGE) asm volatile("cp.async.wait_group 1;" ::: "memory");
        else                asm volatile("cp.async.wait_group 0;" ::: "memory");
        __syncthreads();
        uint32_t so = sb + (uint32_t)(s & 1) * STG128;
        #pragma unroll
        for (int ks = 0; ks < 4; ks++) {
            uint32_t ah[4][4], bh[2][4];
            #pragma unroll
            for (int mi = 0; mi < 4; mi++) {
                int row = wr * 64 + mi * 16 + (lane & 15);
                int ch  = ks * 2 + (lane >> 4);
                ldsm4(so + swz((uint32_t)(row * 128 + ch * 16)), ah[mi]);
            }
            #pragma unroll
            for (int p = 0; p < 2; p++) {
                int row = wc * 32 + p * 16 + ((lane >> 4) << 3) + (lane & 7);
                int ch  = ks * 2 + ((lane >> 3) & 1);
                ldsm4(so + 16384 + swz((uint32_t)(row * 128 + ch * 16)), bh[p]);
            }
            #pragma unroll
            for (int mi = 0; mi < 4; mi++)
                #pragma unroll
                for (int ni = 0; ni < 4; ni++)
                    mma16816(acc[mi][ni], ah[mi], &bh[ni >> 1][(ni & 1) * 2]);
        }
        __syncthreads();
        if (s + 2 < NSTAGE) load_stage(s + 2, s & 1);
    }

    if (mode == 1) {
        #pragma unroll
        for (int mi = 0; mi < 4; mi++)
            #pragma unroll
            for (int ni = 0; ni < 4; ni++) {
                int m0  = rowBase + wr * 64 + mi * 16 + (lane >> 2);
                int col = colBase + wc * 32 + ni * 8 + (lane & 3) * 2;
                size_t i0 = (size_t)m0 * 2048 + col;
                size_t i1 = i0 + (size_t)8 * 2048;
                *(__half2*)(Vout + i0) = __floats2half2_rn(acc[mi][ni][0], acc[mi][ni][1]);
                *(__half2*)(Vout + i1) = __floats2half2_rn(acc[mi][ni][2], acc[mi][ni][3]);
            }
        return;
    }

    __nv_bfloat16* Out = (mode == 0) ? Kout : Qout;
    float sv[4][2], qv[4][2];
    #pragma unroll
    for (int mi = 0; mi < 4; mi++)
        #pragma unroll
        for (int h = 0; h < 2; h++) {
            float s = 0.f, q = 0.f;
            #pragma unroll
            for (int ni = 0; ni < 4; ni++) {
                float a0 = acc[mi][ni][h*2 + 0], a1 = acc[mi][ni][h*2 + 1];
                s += a0 + a1;
                q += a0*a0 + a1*a1;
            }
            s += __shfl_xor_sync(0xffffffffu, s, 1);
            s += __shfl_xor_sync(0xffffffffu, s, 2);
            q += __shfl_xor_sync(0xffffffffu, q, 1);
            q += __shfl_xor_sync(0xffffffffu, q, 2);
            sv[mi][h] = s;
            qv[mi][h] = q;
        }
    __syncthreads();
    float* sArr = (float*)smem;
    float* qArr = ((float*)smem) + 512;
    if ((lane & 3) == 0) {
        #pragma unroll
        for (int mi = 0; mi < 4; mi++)
            #pragma unroll
            for (int h = 0; h < 2; h++) {
                int row = wr * 64 + mi * 16 + (lane >> 2) + h * 8;
                sArr[wc * 128 + row] = sv[mi][h];
                qArr[wc * 128 + row] = qv[mi][h];
            }
    }
    __syncthreads();
    #pragma unroll
    for (int mi = 0; mi < 4; mi++)
        #pragma unroll
        for (int h = 0; h < 2; h++) {
            int row = wr * 64 + mi * 16 + (lane >> 2) + h * 8;
            float S = sArr[row] + sArr[128 + row] + sArr[256 + row] + sArr[384 + row];
            float Q = qArr[row] + qArr[128 + row] + qArr[256 + row] + qArr[384 + row];
            float mean = S * (1.0f / 128.0f);
            float var  = Q * (1.0f / 128.0f) - mean * mean;
            float inv  = rsqrtf(var + EPS);
            int m = rowBase + row;
            #pragma unroll
            for (int ni = 0; ni < 4; ni++) {
                int col = colBase + wc * 32 + ni * 8 + (lane & 3) * 2;
                float a0 = (acc[mi][ni][h*2 + 0] - mean) * inv;
                float a1 = (acc[mi][ni][h*2 + 1] - mean) * inv;
                *(__nv_bfloat162*)(Out + (size_t)m * 2048 + col) = __floats2bfloat162_rn(a0, a1);
            }
        }
}

// ================ sparse attention v4: block=(b,h), V in smem fp16 =============
#define KROWB 264
#define ATT4_SMEM (8192 + 8192 + 32768 + 128 * KROWB)

__global__ __launch_bounds__(256)
void attn4(const __nv_bfloat16* __restrict__ qbf, const __nv_bfloat16* __restrict__ kbf,
           const __half* __restrict__ v, __half* __restrict__ o) {
    extern __shared__ __align__(16) char asmem[];
    float* qs = (float*)asmem;
    float* ps = qs + 2048;
    __half* vsh = (__half*)(asmem + 16384);
    char*  ks = asmem + 16384 + 32768;
    __shared__ float redm[16][4], reds[16][4];
    int b = blockIdx.x, h = blockIdx.y;
    int tid = threadIdx.x, lane = tid & 31;
    int w4 = (tid >> 5) & 3;

    {
        int r = tid >> 4, c = tid & 15;
        uint4 qv = *(const uint4*)(qbf + (size_t)(16*b + r) * D_MOD + h * DHEAD + c * 8);
        const __nv_bfloat162* qb = (const __nv_bfloat162*)&qv;
        float2 f0 = __bfloat1622float2(qb[0]);
        float2 f1 = __bfloat1622float2(qb[1]);
        float2 f2 = __bfloat1622float2(qb[2]);
        float2 f3 = __bfloat1622float2(qb[3]);
        *(float4*)(qs + r * 128 + c * 8)     = make_float4(f0.x, f0.y, f1.x, f1.y);
        *(float4*)(qs + r * 128 + c * 8 + 4) = make_float4(f2.x, f2.y, f3.x, f3.y);
    }
    #pragma unroll
    for (int p = 0; p < 16; p++) {
        int idx = tid + p * 256;
        int j = idx >> 5, c = idx & 31;
        uint2 kk = *(const uint2*)(kbf + (size_t)(b + 16*j) * D_MOD + h * DHEAD + c * 4);
        *(uint2*)(ks + j * KROWB + c * 8) = kk;
    }
    #pragma unroll
    for (int p = 0; p < 16; p++) {
        int idx = tid + p * 256;
        int j = idx >> 5, c = idx & 31;
        uint2 vv = *(const uint2*)(v + (size_t)(b + 16*j) * D_MOD + h * DHEAD + c * 4);
        *(uint2*)(vsh + j * 128 + c * 4) = vv;
    }
    __syncthreads();

    int j = tid & 127, rh = tid >> 7;
    float s[8];
    #pragma unroll
    for (int r8 = 0; r8 < 8; r8++) s[r8] = 0.f;
    #pragma unroll 4
    for (int d4 = 0; d4 < 32; d4++) {
        uint2 kk = *(const uint2*)(ks + j * KROWB + d4 * 8);
        float2 k01 = __bfloat1622float2(*(const __nv_bfloat162*)&kk.x);
        float2 k23 = __bfloat1622float2(*(const __nv_bfloat162*)&kk.y);
        #pragma unroll
        for (int r8 = 0; r8 < 8; r8++) {
            float4 qv = *(const float4*)(qs + (rh * 8 + r8) * 128 + d4 * 4);
            s[r8] += qv.x * k01.x + qv.y * k01.y + qv.z * k23.x + qv.w * k23.y;
        }
    }
    const float SC = 0.08838834764831845f;
    #pragma unroll
    for (int r8 = 0; r8 < 8; r8++) s[r8] *= SC;

    #pragma unroll
    for (int r8 = 0; r8 < 8; r8++) {
        float m = s[r8];
        #pragma unroll
        for (int off = 16; off > 0; off >>= 1) m = fmaxf(m, __shfl_xor_sync(0xffffffffu, m, off));
        if (lane == 0) redm[rh * 8 + r8][w4] = m;
    }
    __syncthreads();
    #pragma unroll
    for (int r8 = 0; r8 < 8; r8++) {
        int r = rh * 8 + r8;
        float mx = fmaxf(fmaxf(redm[r][0], redm[r][1]), fmaxf(redm[r][2], redm[r][3]));
        float p = __expf(s[r8] - mx);
        ps[r * 128 + j] = p;
        float t = p;
        #pragma unroll
        for (int off = 16; off > 0; off >>= 1) t += __shfl_xor_sync(0xffffffffu, t, off);
        if (lane == 0) reds[r][w4] = t;
    }
    __syncthreads();
    float invr[8];
    #pragma unroll
    for (int r8 = 0; r8 < 8; r8++) {
        int r = rh * 8 + r8;
        invr[r8] = 1.0f / fmaxf(reds[r][0] + reds[r][1] + reds[r][2] + reds[r][3], 1e-30f);
    }

    int d = tid & 127;
    float acc[8];
    #pragma unroll
    for (int r8 = 0; r8 < 8; r8++) acc[r8] = 0.f;
    #pragma unroll 4
    for (int jj = 0; jj < 128; jj++) {
        float vv = __half2float(vsh[jj * 128 + d]);
        #pragma unroll
        for (int r8 = 0; r8 < 8; r8++)
            acc[r8] += ps[(rh * 8 + r8) * 128 + jj] * vv;
    }
    #pragma unroll
    for (int r8 = 0; r8 < 8; r8++) {
        int r = rh * 8 + r8;
        o[(size_t)(16*b + r) * D_MOD + h * DHEAD + d] = __float2half_rn(acc[r8] * invr[r8]);
    }
}

// ================ Wo GEMM: 128x128 tiles, split-K=4, atomic epilogue ============
// grid 128: kslice = bid>>5 covers k in [kslice*512, +512) = 8 stages of BK=64.
// rem = bid&31: rowtile = rem>>4 (2 of 128 rows), coltile = rem&15.
#define STG_WO 32768
#define WO_SMEM (2 * STG_WO)

__global__ __launch_bounds__(256)
void gemm_wo(const __half* __restrict__ A, const __half* __restrict__ B,
             float* __restrict__ C) {
    extern __shared__ __align__(1024) char smem[];
    uint32_t sb = smem_u32(smem);
    int bid = blockIdx.x;
    int tid = threadIdx.x;
    int wid = tid >> 5, lane = tid & 31;
    int wr = wid >> 2, wc = wid & 3;
    int kslice = bid >> 5;
    int rem = bid & 31;
    int rowBase = (rem >> 4) * 128, colBase = (rem & 15) * 128;
    size_t kBase = (size_t)kslice * 512;

    float acc[4][4][4];
    #pragma unroll
    for (int mi = 0; mi < 4; mi++)
        #pragma unroll
        for (int ni = 0; ni < 4; ni++)
            #pragma unroll
            for (int r = 0; r < 4; r++) acc[mi][ni][r] = 0.f;

    auto load_stage = [&](int s) {
        uint32_t so = sb + (uint32_t)(s & 1) * STG_WO;
        size_t kof = kBase + (size_t)s * 64;
        #pragma unroll
        for (int p = 0; p < 4; p++) {
            int chunk = tid + p * 256;
            int row = chunk >> 3, c = chunk & 7;
            uint32_t sw = swz((uint32_t)(row * 128 + c * 16));
            cpa16(so + sw,         A + (size_t)(rowBase + row) * 2048 + kof + c * 8);
            cpa16(so + 16384 + sw, B + (size_t)(colBase + row) * 2048 + kof + c * 8);
        }
        asm volatile("cp.async.commit_group;" ::: "memory");
    };

    load_stage(0);
    load_stage(1);

    #pragma unroll 1
    for (int s = 0; s < 8; s++) {
        if (s + 2 < 8) asm volatile("cp.async.wait_group 1;" ::: "memory");
        else           asm volatile("cp.async.wait_group 0;" ::: "memory");
        __syncthreads();
        uint32_t so = sb + (uint32_t)(s & 1) * STG_WO;
        #pragma unroll
        for (int ks = 0; ks < 4; ks++) {
            uint32_t ah[4][4], bh[2][4];
            #pragma unroll
            for (int mi = 0; mi < 4; mi++) {
                int row = wr * 64 + mi * 16 + (lane & 15);
                int ch  = ks * 2 + (lane >> 4);
                ldsm4(so + swz((uint32_t)(row * 128 + ch * 16)), ah[mi]);
            }
            #pragma unroll
            for (int p = 0; p < 2; p++) {
                int row = wc * 32 + p * 16 + ((lane >> 4) << 3) + (lane & 7);
                int ch  = ks * 2 + ((lane >> 3) & 1);
                ldsm4(so + 16384 + swz((uint32_t)(row * 128 + ch * 16)), bh[p]);
            }
            #pragma unroll
            for (int mi = 0; mi < 4; mi++)
                #pragma unroll
                for (int ni = 0; ni < 4; ni++)
                    mma16816(acc[mi][ni], ah[mi], &bh[ni >> 1][(ni & 1) * 2]);
        }
        __syncthreads();
        if (s + 2 < 8) load_stage(s + 2);
    }

    #pragma unroll
    for (int mi = 0; mi < 4; mi++)
        #pragma unroll
        for (int ni = 0; ni < 4; ni++) {
            int m0  = rowBase + wr * 64 + mi * 16 + (lane >> 2);
            int col = colBase + wc * 32 + ni * 8 + (lane & 3) * 2;
            size_t i0 = (size_t)m0 * 2048 + col;
            size_t i1 = i0 + (size_t)8 * 2048;
            atomicAdd(C + i0,     acc[mi][ni][0]);
            atomicAdd(C + i0 + 1, acc[mi][ni][1]);
            atomicAdd(C + i1,     acc[mi][ni][2]);
            atomicAdd(C + i1 + 1, acc[mi][ni][3]);
        }
}

extern "C" void kernel_launch(void* const* d_in, const int* in_sizes, int n_in,
                              void* d_out, int out_size) {
    const float* x  = (const float*)d_in[0];
    const float* Wq = (const float*)d_in[1];
    const float* Wk = (const float*)d_in[2];
    const float* Wv = (const float*)d_in[3];
    const float* Wo = (const float*)d_in[4];
    float* out = (float*)d_out;

    __half *xnh, *wqT, *wkT, *wvT, *woT, *oh, *vh;
    __nv_bfloat16 *kbf, *qbf;
    cudaGetSymbolAddress((void**)&xnh,  g_xnh);
    cudaGetSymbolAddress((void**)&wqT,  g_wqT);
    cudaGetSymbolAddress((void**)&wkT,  g_wkT);
    cudaGetSymbolAddress((void**)&wvT,  g_wvT);
    cudaGetSymbolAddress((void**)&woT,  g_woT);
    cudaGetSymbolAddress((void**)&vh,   g_vh);
    cudaGetSymbolAddress((void**)&kbf,  g_kbf);
    cudaGetSymbolAddress((void**)&qbf,  g_qbf);
    cudaGetSymbolAddress((void**)&oh,   g_oh);

    cudaFuncSetAttribute(proj_gemm, cudaFuncAttributeMaxDynamicSharedMemorySize, G128_SMEM);
    cudaFuncSetAttribute(gemm_wo,   cudaFuncAttributeMaxDynamicSharedMemorySize, WO_SMEM);
    cudaFuncSetAttribute(attn4,     cudaFuncAttributeMaxDynamicSharedMemorySize, ATT4_SMEM);

    // 1) LN -> fp16  +  all weight transposes
    prep<<<2048 + 4 * 1024, 256>>>(x, xnh, Wq, Wk, Wv, Wo, wqT, wkT, wvT, woT);
    // 2) Q+K+V projections; residual init + tail copy hidden (592 = exactly 2 waves)
    proj_gemm<<<592, 256, G128_SMEM>>>(xnh, wkT, wvT, wqT, kbf, vh, qbf, x, out);
    // 3) sparse attention -> fp16 (V staged fp16, 2 CTAs/SM)
    attn4<<<dim3(16, 16), 256, ATT4_SMEM>>>(qbf, kbf, vh, oh);
    // 4) out[0:256] += o @ Wo (128x128 tiles, split-K=4, atomic)
    gemm_wo<<<128, 256, WO_SMEM>>>(oh, woT, out);
}